// round 9
// baseline (speedup 1.0000x reference)
#include <cuda_runtime.h>
#include <cstdint>
#include <math.h>

#define BATCH   4
#define NNODES  4096
#define DIM     64

#define TM      64
#define KT      32
#define KSPLIT  8
#define KLEN    (NNODES / KSPLIT)     // 512
#define NTL     (KLEN / KT)           // 16 k-tiles per CTA
#define THREADS 128

#define TOTE    (BATCH * NNODES * DIM)            // 1M elements
#define SMEM_A  (2 * 8 * TM * 4 * 4)              // 16384 (f32, [st][kc][m][kr])
#define SMEM_B  (2 * KT * 66 * 8)                 // 33792 (uint2 pairs, [st][k][n])
#define SMEM_PROP (SMEM_A + SMEM_B)               // 50176

// ---------------- scratch (device globals) ----------------
__device__ float g_deg[BATCH * NNODES];
__device__ uint2 g_zPA[TOTE];                     // z as (hi,lo) tf32 pairs
__device__ uint2 g_zPB[TOTE];
__device__ float g_part[KSPLIT][TOTE];            // k-split partials (32MB)
__device__ float g_h1[TOTE];
__device__ float g_h2[TOTE];
__device__ float g_h3[TOTE];

// ---------------- helpers ----------------
__device__ __forceinline__ void cp_async16(void* smem_dst, const void* gmem_src) {
    unsigned s = (unsigned)__cvta_generic_to_shared(smem_dst);
    asm volatile("cp.async.cg.shared.global [%0], [%1], 16;\n" :: "r"(s), "l"(gmem_src));
}
__device__ __forceinline__ void cp_commit() {
    asm volatile("cp.async.commit_group;\n");
}
template<int NREM>
__device__ __forceinline__ void cp_wait() {
    asm volatile("cp.async.wait_group %0;\n" :: "n"(NREM));
}
__device__ __forceinline__ uint32_t f2tf32(float a) {
    uint32_t r; asm("cvt.rna.tf32.f32 %0, %1;" : "=r"(r) : "f"(a)); return r;
}
__device__ __forceinline__ void mma_tf32(float* c, const uint32_t* a, const uint32_t* b) {
    asm volatile(
        "mma.sync.aligned.m16n8k8.row.col.f32.tf32.tf32.f32 "
        "{%0,%1,%2,%3}, {%4,%5,%6,%7}, {%8,%9}, {%0,%1,%2,%3};"
        : "+f"(c[0]), "+f"(c[1]), "+f"(c[2]), "+f"(c[3])
        : "r"(a[0]), "r"(a[1]), "r"(a[2]), "r"(a[3]), "r"(b[0]), "r"(b[1]));
}
// truncation split: hi = f with mantissa bits <13 cleared (EXACT tf32 pattern),
// lo = f - hi (passed raw; only its own low bits are HW-interpretation-dependent)
__device__ __forceinline__ void tsplit(float f, uint32_t& hi, uint32_t& lo) {
    hi = __float_as_uint(f) & 0xffffe000u;
    lo = __float_as_uint(f - __uint_as_float(hi));
}

// ---------------- 1) degrees ----------------
__global__ void degree_kernel(const float* __restrict__ graph, float* __restrict__ dvec) {
    const int row = blockIdx.x;
    const float4* g4 = (const float4*)(graph + (size_t)row * NNODES);
    float s = 0.f;
    #pragma unroll
    for (int k = 0; k < NNODES / 4 / 256; k++) {
        float4 v = g4[threadIdx.x + k * 256];
        s += (v.x + v.y) + (v.z + v.w);
    }
    #pragma unroll
    for (int o = 16; o > 0; o >>= 1) s += __shfl_down_sync(0xffffffffu, s, o);
    __shared__ float red[8];
    if ((threadIdx.x & 31) == 0) red[threadIdx.x >> 5] = s;
    __syncthreads();
    if (threadIdx.x == 0) {
        float tot = 1.0f;
        #pragma unroll
        for (int w = 0; w < 8; w++) tot += red[w];
        dvec[row] = 1.0f / (sqrtf(tot) + 1e-7f);
    }
}

// ---------------- 2) z0 = D*x -> rna pairs ----------------
__global__ void scale0_kernel(const float* __restrict__ x) {
    const int i = blockIdx.x * 256 + threadIdx.x;       // f4 index
    float4 v = ((const float4*)x)[i];
    const float d = g_deg[i >> 4];
    v.x *= d; v.y *= d; v.z *= d; v.w *= d;
    uint32_t h0 = f2tf32(v.x), h1 = f2tf32(v.y), h2 = f2tf32(v.z), h3 = f2tf32(v.w);
    uint32_t l0 = f2tf32(v.x - __uint_as_float(h0));
    uint32_t l1 = f2tf32(v.y - __uint_as_float(h1));
    uint32_t l2 = f2tf32(v.z - __uint_as_float(h2));
    uint32_t l3 = f2tf32(v.w - __uint_as_float(h3));
    uint4* dst = (uint4*)g_zPA;
    dst[i * 2 + 0] = make_uint4(h0, l0, h1, l1);
    dst[i * 2 + 1] = make_uint4(h2, l2, h3, l3);
}

// ---------------- 3) propagation partial GEMM ----------------
// part[split] = G[:, kslice] @ z[kslice]      (A fp32 from gmem, split in-regs)
__global__ void __launch_bounds__(THREADS)
prop_kernel(const float* __restrict__ graph, const uint2* __restrict__ zP) {
    extern __shared__ char smem[];
    typedef float ABlk[TM][4];                           // [kc][m][kr]
    typedef uint2 BRow[66];                              // [k][n] pairs, pad 66
    ABlk* As[2] = { (ABlk*)smem,            (ABlk*)(smem + SMEM_A / 2) };
    BRow* Bs[2] = { (BRow*)(smem + SMEM_A), (BRow*)(smem + SMEM_A + SMEM_B / 2) };

    const int tid  = threadIdx.x;
    const int lane = tid & 31;
    const int wid  = tid >> 5;
    const int wm   = (wid >> 1) * 32;
    const int wn   = (wid & 1) * 32;
    const int r0l  = lane >> 2;
    const int krl  = lane & 3;

    const int b = blockIdx.z;
    const int rowBase = blockIdx.x * TM;
    const size_t kbase = (size_t)blockIdx.y * KLEN;
    const float* G = graph + ((size_t)b * NNODES + rowBase) * NNODES;
    const uint2* Z = zP    + (size_t)b * NNODES * DIM;

    float acc[2][4][4];
    #pragma unroll
    for (int i = 0; i < 2; i++)
        #pragma unroll
        for (int j = 0; j < 4; j++)
            #pragma unroll
            for (int r = 0; r < 4; r++) acc[i][j][r] = 0.f;

    auto issue = [&](int t, int st) {
        const size_t k0 = kbase + (size_t)t * KT;
        #pragma unroll
        for (int u = 0; u < 4; u++) {                    // A: 64x32 f32 = 512 16B chunks
            int idx = tid + u * THREADS;
            int m = idx >> 3, kc = idx & 7;
            cp_async16(&As[st][kc][m][0], G + (size_t)m * NNODES + k0 + kc * 4);
        }
        #pragma unroll
        for (int u = 0; u < 8; u++) {                    // B: 32x64 pairs = 1024 chunks
            int idx = tid + u * THREADS;
            int k = idx >> 5, c = idx & 31;
            cp_async16(&Bs[st][k][c * 2], Z + (k0 + k) * DIM + c * 2);
        }
        cp_commit();
    };

    issue(0, 0);
    issue(1, 1);

    for (int t = 0; t < NTL; t++) {
        const int st = t & 1;
        if (t + 1 < NTL) cp_wait<1>(); else cp_wait<0>();
        __syncthreads();

        #pragma unroll
        for (int ks = 0; ks < 4; ks++) {
            const int kc0 = ks * 2, kc1 = ks * 2 + 1;
            uint32_t ahi[2][4], alo[2][4];
            #pragma unroll
            for (int mb = 0; mb < 2; mb++) {
                const int m = wm + mb * 16 + r0l;
                tsplit(As[st][kc0][m    ][krl], ahi[mb][0], alo[mb][0]);
                tsplit(As[st][kc0][m + 8][krl], ahi[mb][1], alo[mb][1]);
                tsplit(As[st][kc1][m    ][krl], ahi[mb][2], alo[mb][2]);
                tsplit(As[st][kc1][m + 8][krl], ahi[mb][3], alo[mb][3]);
            }
            const int kk = ks * 8 + krl;
            uint32_t bhi[4][2], blo[4][2];
            #pragma unroll
            for (int nb = 0; nb < 4; nb++) {
                const int n = wn + nb * 8 + r0l;
                uint2 q0 = Bs[st][kk    ][n];
                uint2 q1 = Bs[st][kk + 4][n];
                bhi[nb][0] = q0.x; blo[nb][0] = q0.y;
                bhi[nb][1] = q1.x; blo[nb][1] = q1.y;
            }
            #pragma unroll
            for (int mb = 0; mb < 2; mb++)
                #pragma unroll
                for (int nb = 0; nb < 4; nb++) {
                    mma_tf32(acc[mb][nb], ahi[mb], bhi[nb]);
                    mma_tf32(acc[mb][nb], ahi[mb], blo[nb]);
                    mma_tf32(acc[mb][nb], alo[mb], bhi[nb]);
                }
        }
        __syncthreads();
        if (t + 2 < NTL) issue(t + 2, st);
    }

    float* P = g_part[blockIdx.y] + (size_t)b * NNODES * DIM;
    #pragma unroll
    for (int mb = 0; mb < 2; mb++) {
        const int r0 = rowBase + wm + mb * 16 + r0l;
        const int r1 = r0 + 8;
        #pragma unroll
        for (int nb = 0; nb < 4; nb++) {
            const int c = wn + nb * 8 + 2 * krl;
            *(float2*)&P[(size_t)r0 * DIM + c] = make_float2(acc[mb][nb][0], acc[mb][nb][1]);
            *(float2*)&P[(size_t)r1 * DIM + c] = make_float2(acc[mb][nb][2], acc[mb][nb][3]);
        }
    }
}

// ---------------- 3b) combine: h = d*(sum parts + z); z_out = d*h (pairs) ------
__global__ void combine_kernel(const uint2* __restrict__ zIn,
                               float* __restrict__ hOut, uint2* __restrict__ zOut) {
    const int i = blockIdx.x * 256 + threadIdx.x;       // f4 index
    const float d = g_deg[i >> 4];

    float4 s = ((const float4*)g_part[0])[i];
    #pragma unroll
    for (int p = 1; p < KSPLIT; p++) {
        float4 sp = ((const float4*)g_part[p])[i];
        s.x += sp.x; s.y += sp.y; s.z += sp.z; s.w += sp.w;
    }

    uint4 zp0 = ((const uint4*)zIn)[i * 2 + 0];
    uint4 zp1 = ((const uint4*)zIn)[i * 2 + 1];
    float z0 = __uint_as_float(zp0.x) + __uint_as_float(zp0.y);
    float z1 = __uint_as_float(zp0.z) + __uint_as_float(zp0.w);
    float z2 = __uint_as_float(zp1.x) + __uint_as_float(zp1.y);
    float z3 = __uint_as_float(zp1.z) + __uint_as_float(zp1.w);

    float4 h;
    h.x = d * (s.x + z0); h.y = d * (s.y + z1);
    h.z = d * (s.z + z2); h.w = d * (s.w + z3);
    ((float4*)hOut)[i] = h;

    float zn0 = d * h.x, zn1 = d * h.y, zn2 = d * h.z, zn3 = d * h.w;
    uint32_t h0 = f2tf32(zn0), h1 = f2tf32(zn1), h2 = f2tf32(zn2), h3 = f2tf32(zn3);
    uint32_t l0 = f2tf32(zn0 - __uint_as_float(h0));
    uint32_t l1 = f2tf32(zn1 - __uint_as_float(h1));
    uint32_t l2 = f2tf32(zn2 - __uint_as_float(h2));
    uint32_t l3 = f2tf32(zn3 - __uint_as_float(h3));
    ((uint4*)zOut)[i * 2 + 0] = make_uint4(h0, l0, h1, l1);
    ((uint4*)zOut)[i * 2 + 1] = make_uint4(h2, l2, h3, l3);
}

// ---------------- 4) out = concat(x,h1,h2,h3) @ W^T + b ----------------
__global__ void __launch_bounds__(256)
out_gemm_kernel(const float* __restrict__ x,
                const float* __restrict__ W,
                const float* __restrict__ bias,
                float* __restrict__ out)
{
    __shared__ float catS[16][256];
    __shared__ float Wt[64][65];

    const int tid = threadIdx.x;
    const int rowBase = blockIdx.x * 16;

    const float* srcs[4] = { x, g_h1, g_h2, g_h3 };
    {
        int r = tid >> 4, f4 = tid & 15;
        #pragma unroll
        for (int s = 0; s < 4; s++) {
            float4 v = *(const float4*)&srcs[s][(size_t)(rowBase + r) * DIM + f4 * 4];
            *(float4*)&catS[r][s * 64 + f4 * 4] = v;
        }
    }

    const int o  = tid & 63;
    const int rg = tid >> 6;

    float acc[4];
    {
        float bv = bias[o];
        #pragma unroll
        for (int j = 0; j < 4; j++) acc[j] = bv;
    }

    for (int fc = 0; fc < 4; fc++) {
        __syncthreads();
        #pragma unroll
        for (int u = 0; u < 4; u++) {
            int i  = tid + u * 256;
            int ro = i >> 4;
            int f4 = i & 15;
            float4 v = *(const float4*)&W[(size_t)ro * 256 + fc * 64 + f4 * 4];
            Wt[f4 * 4 + 0][ro] = v.x;
            Wt[f4 * 4 + 1][ro] = v.y;
            Wt[f4 * 4 + 2][ro] = v.z;
            Wt[f4 * 4 + 3][ro] = v.w;
        }
        __syncthreads();
        #pragma unroll
        for (int fl = 0; fl < 64; fl++) {
            float w = Wt[fl][o];
            #pragma unroll
            for (int j = 0; j < 4; j++)
                acc[j] += catS[rg * 4 + j][fc * 64 + fl] * w;
        }
    }

    #pragma unroll
    for (int j = 0; j < 4; j++)
        out[(size_t)(rowBase + rg * 4 + j) * DIM + o] = acc[j];
}

// ---------------- launch ----------------
template<typename T>
static T* symAddr(const T& symbol) {
    void* p = nullptr;
    cudaGetSymbolAddress(&p, symbol);
    return (T*)p;
}

extern "C" void kernel_launch(void* const* d_in, const int* in_sizes, int n_in,
                              void* d_out, int out_size) {
    const float* x     = (const float*)d_in[0];
    const float* graph = (const float*)d_in[1];
    const float* W     = (const float*)d_in[2];
    const float* bias  = (const float*)d_in[3];
    float* out = (float*)d_out;

    float* deg = (float*)symAddr(g_deg);  (void)deg;
    uint2* zPA = (uint2*)symAddr(g_zPA);
    uint2* zPB = (uint2*)symAddr(g_zPB);
    float* h1  = (float*)symAddr(g_h1);
    float* h2  = (float*)symAddr(g_h2);
    float* h3  = (float*)symAddr(g_h3);

    cudaFuncSetAttribute(prop_kernel,
                         cudaFuncAttributeMaxDynamicSharedMemorySize, SMEM_PROP);

    degree_kernel<<<BATCH * NNODES, 256>>>(graph, deg);
    scale0_kernel<<<TOTE / 4 / 256, 256>>>(x);

    const dim3 gg(NNODES / TM, KSPLIT, BATCH);
    const int cb = TOTE / 4 / 256;

    prop_kernel<<<gg, THREADS, SMEM_PROP>>>(graph, zPA);
    combine_kernel<<<cb, 256>>>(zPA, h1, zPB);

    prop_kernel<<<gg, THREADS, SMEM_PROP>>>(graph, zPB);
    combine_kernel<<<cb, 256>>>(zPB, h2, zPA);

    prop_kernel<<<gg, THREADS, SMEM_PROP>>>(graph, zPA);
    combine_kernel<<<cb, 256>>>(zPA, h3, zPB);

    out_gemm_kernel<<<(BATCH * NNODES) / 16, 256>>>(x, W, bias, out);
}

// round 11
// speedup vs baseline: 1.7917x; 1.7917x over previous
#include <cuda_runtime.h>
#include <cuda_bf16.h>
#include <cstdint>
#include <math.h>

#define BATCH   4
#define NNODES  4096
#define DIM     64

#define TM      64
#define KT      32
#define KSPLIT  8
#define KLEN    (NNODES / KSPLIT)     // 512
#define NTL     (KLEN / KT)           // 16 k-tiles per CTA
#define THREADS 128

#define TOTE    (BATCH * NNODES * DIM)            // 1M elements
#define BPAD    68                                 // 272B row: 16B-multiple (cp.async!)

// ---------------- scratch (device globals) ----------------
__device__ float    g_deg[BATCH * NNODES];
__device__ uint32_t g_zPA[TOTE];                  // z packed (bf16hi<<16 | bf16lo)
__device__ uint32_t g_zPB[TOTE];
__device__ __align__(16) float g_part[KSPLIT][TOTE];   // k-split partials (32MB)
__device__ float    g_h1[TOTE];
__device__ float    g_h2[TOTE];
__device__ float    g_h3[TOTE];

// ---------------- helpers ----------------
__device__ __forceinline__ void cp_async16(void* smem_dst, const void* gmem_src) {
    unsigned s = (unsigned)__cvta_generic_to_shared(smem_dst);
    asm volatile("cp.async.cg.shared.global [%0], [%1], 16;\n" :: "r"(s), "l"(gmem_src));
}
__device__ __forceinline__ void cp_commit() {
    asm volatile("cp.async.commit_group;\n");
}
template<int NREM>
__device__ __forceinline__ void cp_wait() {
    asm volatile("cp.async.wait_group %0;\n" :: "n"(NREM));
}
__device__ __forceinline__ uint32_t prmtb(uint32_t a, uint32_t b, uint32_t sel) {
    uint32_t r; asm("prmt.b32 %0, %1, %2, %3;" : "=r"(r) : "r"(a), "r"(b), "r"(sel));
    return r;
}
// split two f32 into bf16x2 hi pair + bf16x2 lo pair (element0 = f0 in low half)
__device__ __forceinline__ void bsplit2(float f0, float f1, uint32_t& hi, uint32_t& lo) {
    asm("cvt.rn.bf16x2.f32 %0, %1, %2;" : "=r"(hi) : "f"(f1), "f"(f0));
    float h0 = __uint_as_float(hi << 16);
    float h1 = __uint_as_float(hi & 0xffff0000u);
    float l0 = f0 - h0;
    float l1 = f1 - h1;
    asm("cvt.rn.bf16x2.f32 %0, %1, %2;" : "=r"(lo) : "f"(l1), "f"(l0));
}
__device__ __forceinline__ void mma_bf16(float* c, const uint32_t* a, const uint32_t* b) {
    asm volatile(
        "mma.sync.aligned.m16n8k16.row.col.f32.bf16.bf16.f32 "
        "{%0,%1,%2,%3}, {%4,%5,%6,%7}, {%8,%9}, {%0,%1,%2,%3};"
        : "+f"(c[0]), "+f"(c[1]), "+f"(c[2]), "+f"(c[3])
        : "r"(a[0]), "r"(a[1]), "r"(a[2]), "r"(a[3]), "r"(b[0]), "r"(b[1]));
}
// pack f32 -> (bf16hi << 16) | bf16lo
__device__ __forceinline__ uint32_t packpair(float v) {
    __nv_bfloat16 h = __float2bfloat16_rn(v);
    float hf = __bfloat162float(h);
    __nv_bfloat16 l = __float2bfloat16_rn(v - hf);
    return ((uint32_t)__bfloat16_as_ushort(h) << 16) | (uint32_t)__bfloat16_as_ushort(l);
}

// ---------------- 1) degrees ----------------
__global__ void degree_kernel(const float* __restrict__ graph, float* __restrict__ dvec) {
    const int row = blockIdx.x;
    const float4* g4 = (const float4*)(graph + (size_t)row * NNODES);
    float s = 0.f;
    #pragma unroll
    for (int k = 0; k < NNODES / 4 / 256; k++) {
        float4 v = g4[threadIdx.x + k * 256];
        s += (v.x + v.y) + (v.z + v.w);
    }
    #pragma unroll
    for (int o = 16; o > 0; o >>= 1) s += __shfl_down_sync(0xffffffffu, s, o);
    __shared__ float red[8];
    if ((threadIdx.x & 31) == 0) red[threadIdx.x >> 5] = s;
    __syncthreads();
    if (threadIdx.x == 0) {
        float tot = 1.0f;
        #pragma unroll
        for (int w = 0; w < 8; w++) tot += red[w];
        dvec[row] = 1.0f / (sqrtf(tot) + 1e-7f);
    }
}

// ---------------- 2) z0 = D*x -> packed bf16 pairs ----------------
__global__ void scale0_kernel(const float* __restrict__ x) {
    const int i = blockIdx.x * 256 + threadIdx.x;       // f4 index
    float4 v = ((const float4*)x)[i];
    const float d = g_deg[i >> 4];
    uint4 o;
    o.x = packpair(v.x * d); o.y = packpair(v.y * d);
    o.z = packpair(v.z * d); o.w = packpair(v.w * d);
    ((uint4*)g_zPA)[i] = o;
}

// ---------------- 3) propagation partial GEMM (bf16 3-term split) ----------------
// part[split] = G[:, kslice] @ z[kslice]
__global__ void __launch_bounds__(THREADS)
prop_kernel(const float* __restrict__ graph, const uint32_t* __restrict__ zP) {
    __shared__ __align__(16) float    As[2][4][TM][8];   // [st][kc(=k/8)][m][kr]  16KB
    __shared__ __align__(16) uint32_t Bs[2][KT][BPAD];   // [st][k][n] packed pairs

    const int tid  = threadIdx.x;
    const int lane = tid & 31;
    const int wid  = tid >> 5;
    const int wm   = (wid >> 1) * 32;
    const int wn   = (wid & 1) * 32;
    const int r0l  = lane >> 2;              // 0..7
    const int krl  = lane & 3;               // 0..3

    const int b = blockIdx.z;
    const int rowBase = blockIdx.x * TM;
    const size_t kbase = (size_t)blockIdx.y * KLEN;
    const float*    G = graph + ((size_t)b * NNODES + rowBase) * NNODES;
    const uint32_t* Z = zP    + (size_t)b * NNODES * DIM;

    float acc[2][4][4];
    #pragma unroll
    for (int i = 0; i < 2; i++)
        #pragma unroll
        for (int j = 0; j < 4; j++)
            #pragma unroll
            for (int r = 0; r < 4; r++) acc[i][j][r] = 0.f;

    auto issue = [&](int t, int st) {
        const size_t k0 = kbase + (size_t)t * KT;
        #pragma unroll
        for (int u = 0; u < 4; u++) {        // A: 64 rows x 32 f32 = 512 chunks
            int idx = tid + u * THREADS;
            int m = idx >> 3, s = idx & 7;
            int kc = s >> 1, h = s & 1;
            cp_async16(&As[st][kc][m][h * 4], G + (size_t)m * NNODES + k0 + kc * 8 + h * 4);
        }
        #pragma unroll
        for (int u = 0; u < 4; u++) {        // B: 32 rows x 64 uint32 = 512 chunks
            int idx = tid + u * THREADS;
            int k = idx >> 4, c4 = idx & 15;
            cp_async16(&Bs[st][k][c4 * 4], Z + (k0 + k) * DIM + c4 * 4);
        }
        cp_commit();
    };

    issue(0, 0);
    issue(1, 1);

    for (int t = 0; t < NTL; t++) {
        const int st = t & 1;
        if (t + 1 < NTL) cp_wait<1>(); else cp_wait<0>();
        __syncthreads();

        #pragma unroll
        for (int ks = 0; ks < 2; ks++) {                 // two k16 chunks per tile
            const int kc0 = 2 * ks, kc1 = 2 * ks + 1;
            const int kr  = krl * 2;

            uint32_t ahi[2][4], alo[2][4];
            #pragma unroll
            for (int mb = 0; mb < 2; mb++) {
                const int m0 = wm + mb * 16 + r0l;
                const int m1 = m0 + 8;
                float2 f;
                f = *(const float2*)&As[st][kc0][m0][kr];
                bsplit2(f.x, f.y, ahi[mb][0], alo[mb][0]);
                f = *(const float2*)&As[st][kc0][m1][kr];
                bsplit2(f.x, f.y, ahi[mb][1], alo[mb][1]);
                f = *(const float2*)&As[st][kc1][m0][kr];
                bsplit2(f.x, f.y, ahi[mb][2], alo[mb][2]);
                f = *(const float2*)&As[st][kc1][m1][kr];
                bsplit2(f.x, f.y, ahi[mb][3], alo[mb][3]);
            }

            const int kk = ks * 16 + kr;
            uint32_t bhi[4][2], blo[4][2];
            #pragma unroll
            for (int nb = 0; nb < 4; nb++) {
                const int n = wn + nb * 8 + r0l;
                uint32_t p0 = Bs[st][kk    ][n];
                uint32_t p1 = Bs[st][kk + 1][n];
                uint32_t p2 = Bs[st][kk + 8][n];
                uint32_t p3 = Bs[st][kk + 9][n];
                bhi[nb][0] = prmtb(p0, p1, 0x7632); blo[nb][0] = prmtb(p0, p1, 0x5410);
                bhi[nb][1] = prmtb(p2, p3, 0x7632); blo[nb][1] = prmtb(p2, p3, 0x5410);
            }

            #pragma unroll
            for (int mb = 0; mb < 2; mb++)
                #pragma unroll
                for (int nb = 0; nb < 4; nb++) {
                    mma_bf16(acc[mb][nb], ahi[mb], bhi[nb]);
                    mma_bf16(acc[mb][nb], ahi[mb], blo[nb]);
                    mma_bf16(acc[mb][nb], alo[mb], bhi[nb]);
                }
        }
        __syncthreads();
        if (t + 2 < NTL) issue(t + 2, st);
    }

    float* P = g_part[blockIdx.y] + (size_t)b * NNODES * DIM;
    #pragma unroll
    for (int mb = 0; mb < 2; mb++) {
        const int r0 = rowBase + wm + mb * 16 + r0l;
        const int r1 = r0 + 8;
        #pragma unroll
        for (int nb = 0; nb < 4; nb++) {
            const int c = wn + nb * 8 + 2 * krl;
            *(float2*)&P[(size_t)r0 * DIM + c] = make_float2(acc[mb][nb][0], acc[mb][nb][1]);
            *(float2*)&P[(size_t)r1 * DIM + c] = make_float2(acc[mb][nb][2], acc[mb][nb][3]);
        }
    }
}

// ---------------- 3b) combine: h = d*(sum parts + z); z_out packed pairs -------
__global__ void combine_kernel(const uint32_t* __restrict__ zIn,
                               float* __restrict__ hOut, uint32_t* __restrict__ zOut) {
    const int i = blockIdx.x * 256 + threadIdx.x;       // f4 index
    const float d = g_deg[i >> 4];

    float4 s = ((const float4*)g_part[0])[i];
    #pragma unroll
    for (int p = 1; p < KSPLIT; p++) {
        float4 sp = ((const float4*)g_part[p])[i];
        s.x += sp.x; s.y += sp.y; s.z += sp.z; s.w += sp.w;
    }

    uint4 zp = ((const uint4*)zIn)[i];
    float z0 = __uint_as_float(zp.x & 0xffff0000u) + __uint_as_float(zp.x << 16);
    float z1 = __uint_as_float(zp.y & 0xffff0000u) + __uint_as_float(zp.y << 16);
    float z2 = __uint_as_float(zp.z & 0xffff0000u) + __uint_as_float(zp.z << 16);
    float z3 = __uint_as_float(zp.w & 0xffff0000u) + __uint_as_float(zp.w << 16);

    float4 h;
    h.x = d * (s.x + z0); h.y = d * (s.y + z1);
    h.z = d * (s.z + z2); h.w = d * (s.w + z3);
    ((float4*)hOut)[i] = h;

    uint4 o;
    o.x = packpair(d * h.x); o.y = packpair(d * h.y);
    o.z = packpair(d * h.z); o.w = packpair(d * h.w);
    ((uint4*)zOut)[i] = o;
}

// ---------------- 4) out = concat(x,h1,h2,h3) @ W^T + b ----------------
__global__ void __launch_bounds__(256)
out_gemm_kernel(const float* __restrict__ x,
                const float* __restrict__ W,
                const float* __restrict__ bias,
                float* __restrict__ out)
{
    __shared__ float catS[16][256];
    __shared__ float Wt[64][65];

    const int tid = threadIdx.x;
    const int rowBase = blockIdx.x * 16;

    const float* srcs[4] = { x, g_h1, g_h2, g_h3 };
    {
        int r = tid >> 4, f4 = tid & 15;
        #pragma unroll
        for (int s = 0; s < 4; s++) {
            float4 v = *(const float4*)&srcs[s][(size_t)(rowBase + r) * DIM + f4 * 4];
            *(float4*)&catS[r][s * 64 + f4 * 4] = v;
        }
    }

    const int o  = tid & 63;
    const int rg = tid >> 6;

    float acc[4];
    {
        float bv = bias[o];
        #pragma unroll
        for (int j = 0; j < 4; j++) acc[j] = bv;
    }

    for (int fc = 0; fc < 4; fc++) {
        __syncthreads();
        #pragma unroll
        for (int u = 0; u < 4; u++) {
            int i  = tid + u * 256;
            int ro = i >> 4;
            int f4 = i & 15;
            float4 v = *(const float4*)&W[(size_t)ro * 256 + fc * 64 + f4 * 4];
            Wt[f4 * 4 + 0][ro] = v.x;
            Wt[f4 * 4 + 1][ro] = v.y;
            Wt[f4 * 4 + 2][ro] = v.z;
            Wt[f4 * 4 + 3][ro] = v.w;
        }
        __syncthreads();
        #pragma unroll
        for (int fl = 0; fl < 64; fl++) {
            float w = Wt[fl][o];
            #pragma unroll
            for (int j = 0; j < 4; j++)
                acc[j] += catS[rg * 4 + j][fc * 64 + fl] * w;
        }
    }

    #pragma unroll
    for (int j = 0; j < 4; j++)
        out[(size_t)(rowBase + rg * 4 + j) * DIM + o] = acc[j];
}

// ---------------- launch ----------------
template<typename T>
static T* symAddr(const T& symbol) {
    void* p = nullptr;
    cudaGetSymbolAddress(&p, symbol);
    return (T*)p;
}

extern "C" void kernel_launch(void* const* d_in, const int* in_sizes, int n_in,
                              void* d_out, int out_size) {
    const float* x     = (const float*)d_in[0];
    const float* graph = (const float*)d_in[1];
    const float* W     = (const float*)d_in[2];
    const float* bias  = (const float*)d_in[3];
    float* out = (float*)d_out;

    float*    deg = (float*)symAddr(g_deg);
    uint32_t* zPA = (uint32_t*)symAddr(g_zPA);
    uint32_t* zPB = (uint32_t*)symAddr(g_zPB);
    float*    h1  = (float*)symAddr(g_h1);
    float*    h2  = (float*)symAddr(g_h2);
    float*    h3  = (float*)symAddr(g_h3);

    degree_kernel<<<BATCH * NNODES, 256>>>(graph, deg);
    scale0_kernel<<<TOTE / 4 / 256, 256>>>(x);

    const dim3 gg(NNODES / TM, KSPLIT, BATCH);
    const int cb = TOTE / 4 / 256;

    prop_kernel<<<gg, THREADS>>>(graph, zPA);
    combine_kernel<<<cb, 256>>>(zPA, h1, zPB);

    prop_kernel<<<gg, THREADS>>>(graph, zPB);
    combine_kernel<<<cb, 256>>>(zPB, h2, zPA);

    prop_kernel<<<gg, THREADS>>>(graph, zPA);
    combine_kernel<<<cb, 256>>>(zPA, h3, zPB);

    out_gemm_kernel<<<(BATCH * NNODES) / 16, 256>>>(x, W, bias, out);
}